// round 4
// baseline (speedup 1.0000x reference)
#include <cuda_runtime.h>

#define N_EMIT 512
#define ZPL    8
#define ROI    20
#define NPX    400
#define SPL_D  64
#define SPL_H  40
#define SPL_W  40

// Unnormalized PSF values, layout [z][p][e] so K1 stores coalesced (e fastest).
__device__ float g_vals[ZPL * NPX * N_EMIT];

// K1: lane = emitter. One warp evaluates 10 pixels for 32 emitters.
// Grid: 10 pxgroups x 8 z x 16 echunks = 1280 blocks of 128 threads.
// Consecutive blocks share (z, pxgroup) -> identical cells -> L1 broadcast reuse.
__global__ __launch_bounds__(128, 8) void psf_eval(
    const float* __restrict__ pos,
    const float* __restrict__ coefs)
{
    const int echunk = blockIdx.x & 15;
    const int z      = (blockIdx.x >> 4) & 7;
    const int pg     = blockIdx.x >> 7;          // 0..9
    const int w      = threadIdx.x >> 5;
    const int lane   = threadIdx.x & 31;
    const int e      = echunk * 32 + lane;

    const float p0 = pos[e * 3 + 0];   // Y axis (faithful to reference)
    const float p1 = pos[e * 3 + 1];   // X axis
    const float p2 = pos[e * 3 + 2];   // Z axis

    // z terms (constant per thread)
    float pzf = (float)z - p2 + 28.0f;           // SPL_D/2 - ZPL/2
    float fz  = floorf(pzf);
    float dz  = pzf - fz;
    int   iz  = max(0, min((int)fz, SPL_D - 1));
    float dz2 = dz * dz, dz3 = dz2 * dz;

    const int pbase = pg * 40 + w * 10;
    float* vp = g_vals + (size_t)z * NPX * N_EMIT + e;

    #pragma unroll 2
    for (int r = 0; r < 10; r++) {
        const int p = pbase + r;
        const int y = p / 20;
        const int x = p - y * 20;

        float pyf = (float)y - p0 + 10.0f;       // SPL_H/2 - ROI/2
        float fy  = floorf(pyf);
        float dy  = pyf - fy;
        int   iy  = max(0, min((int)fy, SPL_H - 1));

        float pxf = (float)x - p1 + 10.0f;       // SPL_W/2 - ROI/2
        float fx  = floorf(pxf);
        float dx  = pxf - fx;
        int   ix  = max(0, min((int)fx, SPL_W - 1));

        float dx2 = dx * dx, dx3 = dx2 * dx;
        float dy2 = dy * dy, dy3 = dy2 * dy;

        // Generically uniform across the warp -> broadcast L1 wavefronts.
        const float4* cp = (const float4*)(coefs +
            (((size_t)(iz * SPL_H + iy) * SPL_W + ix) << 6));

        float s[4];
        #pragma unroll
        for (int a = 0; a < 4; a++) {
            float4 c0 = cp[a * 4 + 0];
            float4 c1 = cp[a * 4 + 1];
            float4 c2 = cp[a * 4 + 2];
            float4 c3 = cp[a * 4 + 3];
            float t0 = fmaf(c0.w, dx3, fmaf(c0.z, dx2, fmaf(c0.y, dx, c0.x)));
            float t1 = fmaf(c1.w, dx3, fmaf(c1.z, dx2, fmaf(c1.y, dx, c1.x)));
            float t2 = fmaf(c2.w, dx3, fmaf(c2.z, dx2, fmaf(c2.y, dx, c2.x)));
            float t3 = fmaf(c3.w, dx3, fmaf(c3.z, dx2, fmaf(c3.y, dx, c3.x)));
            s[a] = fmaf(t3, dy3, fmaf(t2, dy2, fmaf(t1, dy, t0)));
        }
        float val = fmaf(s[3], dz3, fmaf(s[2], dz2, fmaf(s[1], dz, s[0])));

        vp[(size_t)p * N_EMIT] = val;            // coalesced across lanes
    }
}

// K2: per-(e,z) normalization + transpose [z][p][e] -> out[e][z][p].
// Grid: 16 echunk x 8 z = 128 blocks of 256 threads.
__global__ __launch_bounds__(256) void psf_norm(
    const float* __restrict__ inten,
    const float* __restrict__ bg,
    float* __restrict__ out)
{
    __shared__ float tile[128][33];
    __shared__ float ssum[8][32];
    __shared__ float sscale[32];
    __shared__ float sbg[32];

    const int echunk = blockIdx.x & 15;
    const int z      = blockIdx.x >> 4;
    const int w      = threadIdx.x >> 5;
    const int lane   = threadIdx.x & 31;

    const float* vp = g_vals + (size_t)z * NPX * N_EMIT + echunk * 32;

    // Pass A: plane sums per emitter (lane = emitter, warp = 50-pixel slice)
    float acc = 0.0f;
    #pragma unroll 5
    for (int i = 0; i < 50; i++) {
        int p = w * 50 + i;
        acc += vp[(size_t)p * N_EMIT + lane];
    }
    ssum[w][lane] = acc;
    __syncthreads();
    if (w == 0) {
        float t = 0.0f;
        #pragma unroll
        for (int q = 0; q < 8; q++) t += ssum[q][lane];
        int e = echunk * 32 + lane;
        sscale[lane] = inten[e * ZPL + z] / t;
        sbg[lane]    = bg[e * ZPL + z];
    }
    __syncthreads();

    // Pass B: chunked SMEM transpose + fused scale/background write.
    for (int c = 0; c < 4; c++) {
        const int rows = min(128, NPX - c * 128);
        for (int row = w; row < rows; row += 8)
            tile[row][lane] = vp[(size_t)(c * 128 + row) * N_EMIT + lane];
        __syncthreads();

        #pragma unroll
        for (int q = 0; q < 4; q++) {
            const int   el  = w * 4 + q;
            const int   e   = echunk * 32 + el;
            const float sc  = sscale[el];
            const float bgv = sbg[el];
            float* op = out + ((size_t)e * ZPL + z) * NPX + c * 128;
            #pragma unroll
            for (int m = 0; m < 4; m++) {
                int pp = m * 32 + lane;
                if (pp < rows) op[pp] = fmaf(tile[pp][el], sc, bgv);
            }
        }
        __syncthreads();
    }
}

extern "C" void kernel_launch(void* const* d_in, const int* in_sizes, int n_in,
                              void* d_out, int out_size)
{
    const float* pos   = (const float*)d_in[0];
    const float* inten = (const float*)d_in[1];
    const float* bg    = (const float*)d_in[2];
    const float* coefs = (const float*)d_in[3];

    psf_eval<<<1280, 128>>>(pos, coefs);
    psf_norm<<<128, 256>>>(inten, bg, (float*)d_out);
}

// round 5
// speedup vs baseline: 1.3908x; 1.3908x over previous
#include <cuda_runtime.h>

#define N_EMIT 512
#define ZPL    8
#define ROI    20
#define NPX    400
#define SPL_D  64
#define SPL_H  40
#define SPL_W  40

// One block = (echunk of 32 emitters) x (one z plane). 512 threads = 16 warps.
// lane = emitter, warp w owns pixels [w*25, w*25+25).
__global__ __launch_bounds__(512, 1) void psf_fused(
    const float* __restrict__ pos,
    const float* __restrict__ inten,
    const float* __restrict__ bg,
    const float* __restrict__ coefs,
    float* __restrict__ out)
{
    const int echunk = blockIdx.x & 15;
    const int z      = blockIdx.x >> 4;
    const int w      = threadIdx.x >> 5;
    const int lane   = threadIdx.x & 31;
    const int e      = echunk * 32 + lane;

    __shared__ float sval[200 * 33];   // half-plane transpose tile, pitch 33
    __shared__ float ssum[16][32];
    __shared__ float sscale[32];
    __shared__ float sbg[32];

    const float p0 = pos[e * 3 + 0];   // Y axis (faithful to reference)
    const float p1 = pos[e * 3 + 1];   // X axis
    const float p2 = pos[e * 3 + 2];   // Z axis

    // z terms (constant per thread)
    float pzf = (float)z - p2 + 28.0f;            // SPL_D/2 - ZPL/2
    float fz  = floorf(pzf);
    float dz  = pzf - fz;
    int   iz  = max(0, min((int)fz, SPL_D - 1));
    float dz2 = dz * dz, dz3 = dz2 * dz;
    const int izoff = iz * SPL_H;

    float vals[25];
    float nsum = 0.0f;

    #pragma unroll
    for (int i = 0; i < 25; i++) {
        const int p = w * 25 + i;
        const int y = p / 20;
        const int x = p - y * 20;

        float pyf = (float)y - p0 + 10.0f;        // SPL_H/2 - ROI/2
        float fy  = floorf(pyf);
        float dy  = pyf - fy;
        int   iy  = max(0, min((int)fy, SPL_H - 1));

        float pxf = (float)x - p1 + 10.0f;        // SPL_W/2 - ROI/2
        float fx  = floorf(pxf);
        float dx  = pxf - fx;
        int   ix  = max(0, min((int)fx, SPL_W - 1));

        float dx2 = dx * dx, dx3 = dx2 * dx;
        float dy2 = dy * dy, dy3 = dy2 * dy;

        // Generically uniform address across the warp -> L1 broadcast.
        const float4* cp = (const float4*)(coefs +
            (((size_t)(izoff + iy) * SPL_W + ix) << 6));

        float s0, s1, s2, s3;
        {
            float4 c0 = cp[0], c1 = cp[1], c2 = cp[2], c3 = cp[3];
            float t0 = fmaf(c0.w, dx3, fmaf(c0.z, dx2, fmaf(c0.y, dx, c0.x)));
            float t1 = fmaf(c1.w, dx3, fmaf(c1.z, dx2, fmaf(c1.y, dx, c1.x)));
            float t2 = fmaf(c2.w, dx3, fmaf(c2.z, dx2, fmaf(c2.y, dx, c2.x)));
            float t3 = fmaf(c3.w, dx3, fmaf(c3.z, dx2, fmaf(c3.y, dx, c3.x)));
            s0 = fmaf(t3, dy3, fmaf(t2, dy2, fmaf(t1, dy, t0)));
        }
        {
            float4 c0 = cp[4], c1 = cp[5], c2 = cp[6], c3 = cp[7];
            float t0 = fmaf(c0.w, dx3, fmaf(c0.z, dx2, fmaf(c0.y, dx, c0.x)));
            float t1 = fmaf(c1.w, dx3, fmaf(c1.z, dx2, fmaf(c1.y, dx, c1.x)));
            float t2 = fmaf(c2.w, dx3, fmaf(c2.z, dx2, fmaf(c2.y, dx, c2.x)));
            float t3 = fmaf(c3.w, dx3, fmaf(c3.z, dx2, fmaf(c3.y, dx, c3.x)));
            s1 = fmaf(t3, dy3, fmaf(t2, dy2, fmaf(t1, dy, t0)));
        }
        {
            float4 c0 = cp[8], c1 = cp[9], c2 = cp[10], c3 = cp[11];
            float t0 = fmaf(c0.w, dx3, fmaf(c0.z, dx2, fmaf(c0.y, dx, c0.x)));
            float t1 = fmaf(c1.w, dx3, fmaf(c1.z, dx2, fmaf(c1.y, dx, c1.x)));
            float t2 = fmaf(c2.w, dx3, fmaf(c2.z, dx2, fmaf(c2.y, dx, c2.x)));
            float t3 = fmaf(c3.w, dx3, fmaf(c3.z, dx2, fmaf(c3.y, dx, c3.x)));
            s2 = fmaf(t3, dy3, fmaf(t2, dy2, fmaf(t1, dy, t0)));
        }
        {
            float4 c0 = cp[12], c1 = cp[13], c2 = cp[14], c3 = cp[15];
            float t0 = fmaf(c0.w, dx3, fmaf(c0.z, dx2, fmaf(c0.y, dx, c0.x)));
            float t1 = fmaf(c1.w, dx3, fmaf(c1.z, dx2, fmaf(c1.y, dx, c1.x)));
            float t2 = fmaf(c2.w, dx3, fmaf(c2.z, dx2, fmaf(c2.y, dx, c2.x)));
            float t3 = fmaf(c3.w, dx3, fmaf(c3.z, dx2, fmaf(c3.y, dx, c3.x)));
            s3 = fmaf(t3, dy3, fmaf(t2, dy2, fmaf(t1, dy, t0)));
        }
        float v = fmaf(s3, dz3, fmaf(s2, dz2, fmaf(s1, dz, s0)));
        vals[i] = v;
        nsum   += v;
    }

    // Per-emitter plane sums across the 16 warps
    ssum[w][lane] = nsum;
    __syncthreads();
    if (w == 0) {
        float t = 0.0f;
        #pragma unroll
        for (int q = 0; q < 16; q++) t += ssum[q][lane];
        sscale[lane] = inten[e * ZPL + z] / t;
        sbg[lane]    = bg[e * ZPL + z];
    }
    __syncthreads();

    // Two half-plane chunks: STS (lane-contiguous) -> LDS (pitch-33, conflict-free) -> coalesced STG
    #pragma unroll
    for (int c = 0; c < 2; c++) {
        if ((w >> 3) == c) {
            const int rbase = (w & 7) * 25;
            #pragma unroll
            for (int i = 0; i < 25; i++)
                sval[(rbase + i) * 33 + lane] = vals[i];
        }
        __syncthreads();

        // warp w writes emitters 2w and 2w+1, 200 contiguous floats each
        #pragma unroll
        for (int q = 0; q < 2; q++) {
            const int   el  = w * 2 + q;
            const int   eo  = echunk * 32 + el;
            const float sc  = sscale[el];
            const float bgv = sbg[el];
            float* op = out + ((size_t)eo * ZPL + z) * NPX + c * 200;
            #pragma unroll
            for (int m = 0; m < 7; m++) {
                int pp = m * 32 + lane;
                if (pp < 200) op[pp] = fmaf(sval[pp * 33 + el], sc, bgv);
            }
        }
        __syncthreads();
    }
}

extern "C" void kernel_launch(void* const* d_in, const int* in_sizes, int n_in,
                              void* d_out, int out_size)
{
    const float* pos   = (const float*)d_in[0];
    const float* inten = (const float*)d_in[1];
    const float* bg    = (const float*)d_in[2];
    const float* coefs = (const float*)d_in[3];

    psf_fused<<<128, 512>>>(pos, inten, bg, coefs, (float*)d_out);
}